// round 17
// baseline (speedup 1.0000x reference)
#include <cuda_runtime.h>

// SparseBiasDiagUnfolder — FINAL config + streaming stores (__stcs).
// One wave: 146 blocks x 896 threads (28 warps/CTA), 2 window-rows per warp,
// div-free and fully 32-bit index math. Output is write-once -> evict-first
// streaming stores keep the L2 free for the (replay-resident) input band.
//
//   adj: (B=2, N=2048, N=2048, F=16) fp32; starts 0,4,...,2040 (511);
//   out (B, 511, 56*16).
//
// Structure:
//   * 8176 window rows (b, s, ii); row = adj[b, 4s+ii, 4s+jj, :], jj=0..7
//     -> one 512B CONTIGUOUS run per row. 2 rows/warp -> 4088 warps =
//     146 CTAs x 28 warps exactly (single wave on 148 SMs).
//   * Loads: lane l reads float4 base+l -> 2 independent fully-coalesced
//     512B LDG.128 batched before any store.
//   * Stores: per row, 28 lanes (jj != ii) write a contiguous 448B run
//     (diagonal chunk dropped, pos = ii*7 + jj - (jj>ii)), via __stcs.
//   * Index math: bs = w>>2 < 1022 so b = (bs>=511) — no division; all
//     addresses fit 32-bit (max adj float4 index = 2^25).
//
// Tuning summary (17 benches): one-wave grid was the only significant win
// (6.88 -> ~6.5). rows/warp {1,2,4}, warps/CTA {8,14,28}, input- vs
// output-centric forms all draw from the same 6.50-6.88 band (identical
// source printed 6.496/6.656/6.880). All SOL pipes <11%; residual wall
// time is graph-replay/launch floor.

namespace {
constexpr int N        = 2048;
constexpr int NSTARTS  = 511;
constexpr int WARPS_PER_BLOCK = 28;
constexpr int THREADS  = WARPS_PER_BLOCK * 32;   // 896
constexpr int BLOCKS   = 146;                    // 4088 warps = 8176 rows / 2
}

__global__ void __launch_bounds__(THREADS)
sparse_diag_unfold_kernel(const float4* __restrict__ adj, float4* __restrict__ out)
{
    const unsigned gt   = blockIdx.x * THREADS + threadIdx.x;
    const unsigned w    = gt >> 5;                 // 0..4087
    const unsigned lane = gt & 31;

    const unsigned bs      = w >> 2;               // b*511 + s, < 1022
    const unsigned ii_base = (w & 3) * 2;          // 0,2,4,6

    const unsigned b = (bs >= NSTARTS);            // no division
    const unsigned s = bs - b * NSTARTS;

    // 32-bit float4 base index of row (bs, ii_base):
    //   b*N*N*4 + s*(N+1)*16 + ii_base*N*4 + lane   (max ~2^25)
    const unsigned base0 = b * (N * N * 4u)
                         + s * ((N + 1) * 16u)
                         + ii_base * (N * 4u)
                         + lane;

    const unsigned jj = lane >> 2;
    const unsigned v  = lane & 3;

    // 2 independent coalesced 512B loads, batched (front-batched MLP).
    float4 vals[2];
    #pragma unroll
    for (int k = 0; k < 2; k++)
        vals[k] = adj[base0 + (unsigned)k * (N * 4u)];

    const unsigned out_base = bs * (56u * 4u);
    #pragma unroll
    for (int k = 0; k < 2; k++) {
        const unsigned ii = ii_base + k;
        if (jj != ii) {
            const unsigned pos = ii * 7u + jj - (jj > ii);   // 0..55
            __stcs(&out[out_base + pos * 4u + v], vals[k]);  // streaming store
        }
    }
}

extern "C" void kernel_launch(void* const* d_in, const int* in_sizes, int n_in,
                              void* d_out, int out_size)
{
    const float4* adj = (const float4*)d_in[0];
    float4* out = (float4*)d_out;
    sparse_diag_unfold_kernel<<<BLOCKS, THREADS>>>(adj, out);
}